// round 1
// baseline (speedup 1.0000x reference)
#include <cuda_runtime.h>
#include <math.h>

#define NN    10000
#define IND   512
#define D1    512      // HEADS*HID
#define HEADS 8
#define HID   64
#define D2    64
#define ODIM  5000
#define NE    160000
#define ET    170000   // NE + NN self loops
#define NEG   0.2f

// ---------------- scratch (static device globals; no allocation) ------------
__device__ float    g_xl1[(size_t)NN * D1];
__device__ float    g_xr1[(size_t)NN * D1];
__device__ float    g_h1 [(size_t)NN * D1];
__device__ float    g_e1 [(size_t)ET * HEADS];
__device__ float    g_xl2[(size_t)NN * D2];
__device__ float    g_xr2[(size_t)NN * D2];
__device__ float    g_h2 [(size_t)NN * D2];
__device__ float    g_e2 [ET];
__device__ unsigned g_m1 [NN * HEADS];
__device__ float    g_s1 [NN * HEADS];
__device__ unsigned g_m2 [NN];
__device__ float    g_s2 [NN];
__device__ int      g_deg[NN];
__device__ int      g_off[NN + 1];
__device__ int      g_cur[NN];
__device__ int      g_perm[ET];
__device__ int      g_is64;

// ---------------- helpers ---------------------------------------------------
__device__ __forceinline__ int eidx(const void* ei, int i) {
    return g_is64 ? (int)((const long long*)ei)[i] : ((const int*)ei)[i];
}
__device__ __forceinline__ int esrc(const void* ei, int w) {
    return (w < NE) ? eidx(ei, w) : (w - NE);
}
__device__ __forceinline__ int edst(const void* ei, int w) {
    return (w < NE) ? eidx(ei, NE + w) : (w - NE);
}
// order-preserving float<->uint for atomicMax
__device__ __forceinline__ unsigned fenc(float f) {
    unsigned b = __float_as_uint(f);
    return (b & 0x80000000u) ? ~b : (b | 0x80000000u);
}
__device__ __forceinline__ float fdec(unsigned u) {
    return (u & 0x80000000u) ? __uint_as_float(u ^ 0x80000000u)
                             : __uint_as_float(~u);
}
__device__ __forceinline__ float lrelu(float v) { return v > 0.f ? v : NEG * v; }

// ---------------- int64/int32 edge-index detection --------------------------
__global__ void detect_kernel(const void* ei) {
    const long long* p = (const long long*)ei;
    int ok = 1;
    for (int i = 0; i < 64; i++) {
        long long v = p[i];
        if (v < 0 || v >= NN) { ok = 0; break; }
    }
    g_is64 = ok;
}

// ---------------- init ------------------------------------------------------
__global__ void init_kernel() {
    int i = blockIdx.x * blockDim.x + threadIdx.x;
    if (i < NN * HEADS) { g_m1[i] = 0u; g_s1[i] = 0.f; }
    if (i < NN)         { g_deg[i] = 0; g_m2[i] = 0u; g_s2[i] = 0.f; }
}

// ---------------- generic SGEMM: C[M,Nc] = A[M,K] @ W[Nc,K]^T + bias --------
#define BM 128
#define BN 128
#define BK 8
__global__ __launch_bounds__(256) void sgemm_bias(
    const float* __restrict__ A, const float* __restrict__ W,
    const float* __restrict__ bias, float* __restrict__ C,
    int M, int Nc, int K)
{
    __shared__ float As[BK][BM];
    __shared__ float Bs[BK][BN];
    int tid = threadIdx.x;
    int rowBase = blockIdx.y * BM, colBase = blockIdx.x * BN;
    int lr = tid >> 1, lk = (tid & 1) * 4;
    int tx = tid & 15, ty = tid >> 4;
    float acc[8][8];
    #pragma unroll
    for (int i = 0; i < 8; i++)
        #pragma unroll
        for (int j = 0; j < 8; j++) acc[i][j] = 0.f;

    for (int k0 = 0; k0 < K; k0 += BK) {
        int gr = rowBase + lr;
        float4 av = make_float4(0.f, 0.f, 0.f, 0.f);
        if (gr < M) av = *(const float4*)(A + (size_t)gr * K + k0 + lk);
        As[lk + 0][lr] = av.x; As[lk + 1][lr] = av.y;
        As[lk + 2][lr] = av.z; As[lk + 3][lr] = av.w;

        int wr = colBase + lr;
        float4 bv = make_float4(0.f, 0.f, 0.f, 0.f);
        if (wr < Nc) bv = *(const float4*)(W + (size_t)wr * K + k0 + lk);
        Bs[lk + 0][lr] = bv.x; Bs[lk + 1][lr] = bv.y;
        Bs[lk + 2][lr] = bv.z; Bs[lk + 3][lr] = bv.w;
        __syncthreads();

        #pragma unroll
        for (int kk = 0; kk < BK; kk++) {
            float a[8], b[8];
            #pragma unroll
            for (int i = 0; i < 8; i++) a[i] = As[kk][ty * 8 + i];
            #pragma unroll
            for (int j = 0; j < 8; j++) b[j] = Bs[kk][tx * 8 + j];
            #pragma unroll
            for (int i = 0; i < 8; i++)
                #pragma unroll
                for (int j = 0; j < 8; j++) acc[i][j] = fmaf(a[i], b[j], acc[i][j]);
        }
        __syncthreads();
    }
    #pragma unroll
    for (int i = 0; i < 8; i++) {
        int r = rowBase + ty * 8 + i;
        if (r >= M) continue;
        #pragma unroll
        for (int j = 0; j < 8; j++) {
            int c = colBase + tx * 8 + j;
            if (c < Nc) C[(size_t)r * Nc + c] = acc[i][j] + bias[c];
        }
    }
}

// ---------------- layer-1 edge scores (warp per edge) -----------------------
__global__ __launch_bounds__(256) void edge_scores1(const void* ei,
                                                    const float* __restrict__ att)
{
    int gw = (blockIdx.x * blockDim.x + threadIdx.x) >> 5;
    int lane = threadIdx.x & 31;
    if (gw >= ET) return;
    int s = esrc(ei, gw), d = edst(ei, gw);
    const float* xls = g_xl1 + (size_t)s * D1;
    const float* xrd = g_xr1 + (size_t)d * D1;
    #pragma unroll
    for (int h = 0; h < HEADS; h++) {
        int c = h * HID + lane;
        float v0 = lrelu(xls[c] + xrd[c]) * att[c];
        float v1 = lrelu(xls[c + 32] + xrd[c + 32]) * att[c + 32];
        float sum = v0 + v1;
        #pragma unroll
        for (int o = 16; o; o >>= 1) sum += __shfl_xor_sync(0xffffffffu, sum, o);
        if (lane == 0) g_e1[(size_t)gw * HEADS + h] = sum;
    }
}

// ---------------- CSR build -------------------------------------------------
__global__ void deg_kernel(const void* ei) {
    int w = blockIdx.x * blockDim.x + threadIdx.x;
    if (w >= ET) return;
    atomicAdd(&g_deg[edst(ei, w)], 1);
}

__global__ __launch_bounds__(1024) void scan_kernel() {
    __shared__ int sh[1024];
    __shared__ int carry_s;
    int t = threadIdx.x;
    if (t == 0) carry_s = 0;
    __syncthreads();
    for (int base = 0; base < NN; base += 1024) {
        int v = (base + t < NN) ? g_deg[base + t] : 0;
        sh[t] = v;
        __syncthreads();
        for (int o = 1; o < 1024; o <<= 1) {
            int add = (t >= o) ? sh[t - o] : 0;
            __syncthreads();
            sh[t] += add;
            __syncthreads();
        }
        int excl = sh[t] - v + carry_s;
        if (base + t < NN) { g_off[base + t] = excl; g_cur[base + t] = excl; }
        __syncthreads();
        if (t == 0) carry_s += sh[1023];
        __syncthreads();
    }
    if (t == 0) g_off[NN] = carry_s;
}

__global__ void scatter_kernel(const void* ei) {
    int w = blockIdx.x * blockDim.x + threadIdx.x;
    if (w >= ET) return;
    int pos = atomicAdd(&g_cur[edst(ei, w)], 1);
    g_perm[pos] = w;
}

// ---------------- layer-1 softmax stats -------------------------------------
__global__ void max1_kernel(const void* ei) {
    int i = blockIdx.x * blockDim.x + threadIdx.x;
    if (i >= ET * HEADS) return;
    int e = i >> 3, h = i & 7;
    int d = edst(ei, e);
    atomicMax(&g_m1[d * HEADS + h], fenc(g_e1[i]));
}
__global__ void sum1_kernel(const void* ei) {
    int i = blockIdx.x * blockDim.x + threadIdx.x;
    if (i >= ET * HEADS) return;
    int e = i >> 3, h = i & 7;
    int d = edst(ei, e);
    float m = fdec(g_m1[d * HEADS + h]);
    atomicAdd(&g_s1[d * HEADS + h], expf(g_e1[i] - m));
}

// ---------------- layer-1 aggregation (block per dst) -----------------------
__global__ __launch_bounds__(256) void aggregate1(const void* ei,
                                                  const float* __restrict__ bias)
{
    int d = blockIdx.x;
    int beg = g_off[d], end = g_off[d + 1];
    int t = threadIdx.x;
    __shared__ float wsh[32 * 8];
    __shared__ int   ssh[32];
    float mh  = fdec(g_m1[d * HEADS + (t & 7)]);
    float svh = 1.f / (g_s1[d * HEADS + (t & 7)] + 1e-16f);
    float acc0 = 0.f, acc1 = 0.f;
    int h0 = t >> 6, h1 = (t + 256) >> 6;
    for (int ch = beg; ch < end; ch += 32) {
        int nc = min(32, end - ch);
        int i = t >> 3, h = t & 7;
        if (i < nc) {
            int eid = g_perm[ch + i];
            wsh[i * 8 + h] = expf(g_e1[(size_t)eid * HEADS + h] - mh) * svh;
            if (h == 0) ssh[i] = esrc(ei, eid);
        }
        __syncthreads();
        for (int i2 = 0; i2 < nc; i2++) {
            const float* xs = g_xl1 + (size_t)ssh[i2] * D1;
            acc0 += wsh[i2 * 8 + h0] * xs[t];
            acc1 += wsh[i2 * 8 + h1] * xs[t + 256];
        }
        __syncthreads();
    }
    g_h1[(size_t)d * D1 + t]       = fmaxf(acc0 + bias[t], 0.f);
    g_h1[(size_t)d * D1 + t + 256] = fmaxf(acc1 + bias[t + 256], 0.f);
}

// ---------------- layer-2 edge scores (warp per edge, 1 head) ---------------
__global__ __launch_bounds__(256) void edge_scores2(const void* ei,
                                                    const float* __restrict__ att)
{
    int gw = (blockIdx.x * blockDim.x + threadIdx.x) >> 5;
    int lane = threadIdx.x & 31;
    if (gw >= ET) return;
    int s = esrc(ei, gw), d = edst(ei, gw);
    const float* xls = g_xl2 + (size_t)s * D2;
    const float* xrd = g_xr2 + (size_t)d * D2;
    float v0 = lrelu(xls[lane] + xrd[lane]) * att[lane];
    float v1 = lrelu(xls[lane + 32] + xrd[lane + 32]) * att[lane + 32];
    float sum = v0 + v1;
    #pragma unroll
    for (int o = 16; o; o >>= 1) sum += __shfl_xor_sync(0xffffffffu, sum, o);
    if (lane == 0) g_e2[gw] = sum;
}

__global__ void max2_kernel(const void* ei) {
    int w = blockIdx.x * blockDim.x + threadIdx.x;
    if (w >= ET) return;
    atomicMax(&g_m2[edst(ei, w)], fenc(g_e2[w]));
}
__global__ void sum2_kernel(const void* ei) {
    int w = blockIdx.x * blockDim.x + threadIdx.x;
    if (w >= ET) return;
    int d = edst(ei, w);
    atomicAdd(&g_s2[d], expf(g_e2[w] - fdec(g_m2[d])));
}

// ---------------- layer-2 aggregation (block per dst, 64 thr) ---------------
__global__ __launch_bounds__(64) void aggregate2(const void* ei,
                                                 const float* __restrict__ bias)
{
    int d = blockIdx.x;
    int beg = g_off[d], end = g_off[d + 1];
    int t = threadIdx.x;
    __shared__ float wsh[64];
    __shared__ int   ssh[64];
    float mh = fdec(g_m2[d]);
    float sv = 1.f / (g_s2[d] + 1e-16f);
    float acc = 0.f;
    for (int ch = beg; ch < end; ch += 64) {
        int nc = min(64, end - ch);
        if (t < nc) {
            int eid = g_perm[ch + t];
            wsh[t] = expf(g_e2[eid] - mh) * sv;
            ssh[t] = esrc(ei, eid);
        }
        __syncthreads();
        for (int i = 0; i < nc; i++)
            acc += wsh[i] * g_xl2[(size_t)ssh[i] * D2 + t];
        __syncthreads();
    }
    g_h2[(size_t)d * D2 + t] = fmaxf(acc + bias[t], 0.f);
}

// ---------------- launch ----------------------------------------------------
extern "C" void kernel_launch(void* const* d_in, const int* in_sizes, int n_in,
                              void* d_out, int out_size)
{
    const float* x    = (const float*)d_in[0];
    const void*  ei   = d_in[1];
    const float* W1l  = (const float*)d_in[2];
    const float* b1l  = (const float*)d_in[3];
    const float* W1r  = (const float*)d_in[4];
    const float* b1r  = (const float*)d_in[5];
    const float* att1 = (const float*)d_in[6];
    const float* bias1= (const float*)d_in[7];
    const float* W2l  = (const float*)d_in[8];
    const float* b2l  = (const float*)d_in[9];
    const float* W2r  = (const float*)d_in[10];
    const float* b2r  = (const float*)d_in[11];
    const float* att2 = (const float*)d_in[12];
    const float* bias2= (const float*)d_in[13];
    const float* fcw  = (const float*)d_in[14];
    const float* fcb  = (const float*)d_in[15];
    float* out = (float*)d_out;

    void *p_xl1, *p_xr1, *p_h1, *p_xl2, *p_xr2, *p_h2;
    cudaGetSymbolAddress(&p_xl1, g_xl1);
    cudaGetSymbolAddress(&p_xr1, g_xr1);
    cudaGetSymbolAddress(&p_h1,  g_h1);
    cudaGetSymbolAddress(&p_xl2, g_xl2);
    cudaGetSymbolAddress(&p_xr2, g_xr2);
    cudaGetSymbolAddress(&p_h2,  g_h2);

    detect_kernel<<<1, 1>>>(ei);
    init_kernel<<<(NN * HEADS + 255) / 256, 256>>>();

    dim3 g1((D1 + BN - 1) / BN, (NN + BM - 1) / BM);
    sgemm_bias<<<g1, 256>>>(x, W1l, b1l, (float*)p_xl1, NN, D1, IND);
    sgemm_bias<<<g1, 256>>>(x, W1r, b1r, (float*)p_xr1, NN, D1, IND);

    int eb = (ET * 32 + 255) / 256;
    edge_scores1<<<eb, 256>>>(ei, att1);

    deg_kernel<<<(ET + 255) / 256, 256>>>(ei);
    scan_kernel<<<1, 1024>>>();
    scatter_kernel<<<(ET + 255) / 256, 256>>>(ei);

    max1_kernel<<<(ET * HEADS + 255) / 256, 256>>>(ei);
    sum1_kernel<<<(ET * HEADS + 255) / 256, 256>>>(ei);
    aggregate1<<<NN, 256>>>(ei, bias1);

    dim3 g2((D2 + BN - 1) / BN, (NN + BM - 1) / BM);
    sgemm_bias<<<g2, 256>>>((const float*)p_h1, W2l, b2l, (float*)p_xl2, NN, D2, D1);
    sgemm_bias<<<g2, 256>>>((const float*)p_h1, W2r, b2r, (float*)p_xr2, NN, D2, D1);

    edge_scores2<<<eb, 256>>>(ei, att2);
    max2_kernel<<<(ET + 255) / 256, 256>>>(ei);
    sum2_kernel<<<(ET + 255) / 256, 256>>>(ei);
    aggregate2<<<NN, 64>>>(ei, bias2);

    dim3 g3((ODIM + BN - 1) / BN, (NN + BM - 1) / BM);
    sgemm_bias<<<g3, 256>>>((const float*)p_h2, fcw, fcb, out, NN, ODIM, D2);
}

// round 4
// speedup vs baseline: 2.3339x; 2.3339x over previous
#include <cuda_runtime.h>
#include <cstdint>
#include <math.h>

#define NN    10000
#define IND   512
#define D1    512      // HEADS*HID
#define HEADS 8
#define HID   64
#define D2    64
#define ODIM  5000
#define NE    160000
#define ET    170000   // NE + NN self loops
#define NEG   0.2f

// ---------------- scratch (static device globals; no allocation) ------------
__device__ float    g_xl1[(size_t)NN * D1];
__device__ float    g_xr1[(size_t)NN * D1];
__device__ float    g_h1 [(size_t)NN * D1];
__device__ float    g_e1 [(size_t)ET * HEADS];
__device__ float    g_xl2[(size_t)NN * D2];
__device__ float    g_xr2[(size_t)NN * D2];
__device__ float    g_h2 [(size_t)NN * D2];
__device__ float    g_e2 [ET];
__device__ unsigned g_m1 [NN * HEADS];
__device__ float    g_s1 [NN * HEADS];
__device__ unsigned g_m2 [NN];
__device__ float    g_s2 [NN];
__device__ int      g_deg[NN];
__device__ int      g_off[NN + 1];
__device__ int      g_cur[NN];
__device__ int      g_perm[ET];
__device__ int      g_is64;

// ---------------- helpers ---------------------------------------------------
__device__ __forceinline__ int eidx(const void* ei, int i) {
    return g_is64 ? (int)((const long long*)ei)[i] : ((const int*)ei)[i];
}
__device__ __forceinline__ int esrc(const void* ei, int w) {
    return (w < NE) ? eidx(ei, w) : (w - NE);
}
__device__ __forceinline__ int edst(const void* ei, int w) {
    return (w < NE) ? eidx(ei, NE + w) : (w - NE);
}
__device__ __forceinline__ unsigned fenc(float f) {
    unsigned b = __float_as_uint(f);
    return (b & 0x80000000u) ? ~b : (b | 0x80000000u);
}
__device__ __forceinline__ float fdec(unsigned u) {
    return (u & 0x80000000u) ? __uint_as_float(u ^ 0x80000000u)
                             : __uint_as_float(~u);
}
__device__ __forceinline__ float lrelu(float v) { return v > 0.f ? v : NEG * v; }
__device__ __forceinline__ uint32_t f2tf32(float f) {
    uint32_t r; asm("cvt.rna.tf32.f32 %0, %1;" : "=r"(r) : "f"(f)); return r;
}

// ---------------- tf32 mma.sync GEMM ----------------------------------------
// C[M,Nc] = A[M,K] @ W[Nc,K]^T + bias ; W / bias / C split at `split` into
// (Wa,ba,Ca | Wb,bb,Cb). Tile 128x128, BK=32. 8 warps, each 64x32 warp-tile
// of m16n8k8 tf32 MMAs. Requires K % 32 == 0.
#define BK 32
#define STR 36   // smem row stride (floats): bank = (4*row + q) % 32, conflict-free

__device__ __forceinline__ void mma16n8k8(float* c, const uint32_t* a, const uint32_t* b) {
    asm volatile("mma.sync.aligned.m16n8k8.row.col.f32.tf32.tf32.f32 "
        "{%0,%1,%2,%3}, {%4,%5,%6,%7}, {%8,%9}, {%0,%1,%2,%3};"
        : "+f"(c[0]), "+f"(c[1]), "+f"(c[2]), "+f"(c[3])
        : "r"(a[0]), "r"(a[1]), "r"(a[2]), "r"(a[3]), "r"(b[0]), "r"(b[1]));
}

__global__ __launch_bounds__(256) void tc_gemm(
    const float* __restrict__ A,
    const float* __restrict__ Wa, const float* __restrict__ Wb,
    const float* __restrict__ ba, const float* __restrict__ bb,
    float* __restrict__ Ca, float* __restrict__ Cb,
    int split, int M, int Nc, int K)
{
    __shared__ uint32_t As[128 * STR];
    __shared__ uint32_t Bs[128 * STR];

    int tid = threadIdx.x, wid = tid >> 5, lane = tid & 31;
    int g = lane >> 2, q = lane & 3;          // fragment group / quad
    int wm = wid >> 2, wn = wid & 3;          // warp tile: 2x4 grid of 64x32
    int rowBase = blockIdx.y * 128, colBase = blockIdx.x * 128;

    // global staging pointers: thread loads 16 floats of one row per k-chunk
    int srow = tid >> 1;                      // 0..127
    int scol = (tid & 1) * 16;
    int garow = rowBase + srow;
    int gbrow = colBase + srow;
    const float* agp = (garow < M) ? A + (size_t)garow * K + scol : nullptr;
    const float* bgp = nullptr;
    if (gbrow < Nc)
        bgp = (gbrow < split) ? Wa + (size_t)gbrow * K + scol
                              : Wb + (size_t)(gbrow - split) * K + scol;

    float acc[4][4][4];
    #pragma unroll
    for (int i = 0; i < 4; i++)
        #pragma unroll
        for (int j = 0; j < 4; j++)
            #pragma unroll
            for (int r = 0; r < 4; r++) acc[i][j][r] = 0.f;

    for (int k0 = 0; k0 < K; k0 += BK) {
        // stage A,B chunk -> smem (converted to tf32 bits)
        #pragma unroll
        for (int j = 0; j < 4; j++) {
            float4 av = agp ? *(const float4*)(agp + k0 + j * 4)
                            : make_float4(0.f, 0.f, 0.f, 0.f);
            float4 bv = bgp ? *(const float4*)(bgp + k0 + j * 4)
                            : make_float4(0.f, 0.f, 0.f, 0.f);
            uint32_t* ad = &As[srow * STR + scol + j * 4];
            uint32_t* bd = &Bs[srow * STR + scol + j * 4];
            ad[0] = f2tf32(av.x); ad[1] = f2tf32(av.y);
            ad[2] = f2tf32(av.z); ad[3] = f2tf32(av.w);
            bd[0] = f2tf32(bv.x); bd[1] = f2tf32(bv.y);
            bd[2] = f2tf32(bv.z); bd[3] = f2tf32(bv.w);
        }
        __syncthreads();

        #pragma unroll
        for (int kk = 0; kk < BK; kk += 8) {
            uint32_t afr[4][4], bfr[4][2];
            #pragma unroll
            for (int i = 0; i < 4; i++) {
                int r = wm * 64 + i * 16 + g;
                afr[i][0] = As[(r    ) * STR + kk + q    ];
                afr[i][1] = As[(r + 8) * STR + kk + q    ];
                afr[i][2] = As[(r    ) * STR + kk + q + 4];
                afr[i][3] = As[(r + 8) * STR + kk + q + 4];
            }
            #pragma unroll
            for (int j = 0; j < 4; j++) {
                int n = wn * 32 + j * 8 + g;
                bfr[j][0] = Bs[n * STR + kk + q    ];
                bfr[j][1] = Bs[n * STR + kk + q + 4];
            }
            #pragma unroll
            for (int i = 0; i < 4; i++)
                #pragma unroll
                for (int j = 0; j < 4; j++)
                    mma16n8k8(acc[i][j], afr[i], bfr[j]);
        }
        __syncthreads();
    }

    // epilogue: direct global stores (float2 per half-tile row)
    #pragma unroll
    for (int i = 0; i < 4; i++) {
        int r0 = rowBase + wm * 64 + i * 16 + g;
        #pragma unroll
        for (int j = 0; j < 4; j++) {
            int c = colBase + wn * 32 + j * 8 + q * 2;
            if (c >= Nc) continue;
            float bv0, bv1;
            float* dst0; float* dst1;
            if (c < split) {
                bv0 = ba[c]; bv1 = ba[c + 1];
                dst0 = Ca + (size_t)r0 * split + c;
                dst1 = Ca + (size_t)(r0 + 8) * split + c;
            } else {
                int cc = c - split; int w2 = Nc - split;
                bv0 = bb[cc]; bv1 = bb[cc + 1];
                dst0 = Cb + (size_t)r0 * w2 + cc;
                dst1 = Cb + (size_t)(r0 + 8) * w2 + cc;
            }
            if (r0 < M)
                *(float2*)dst0 = make_float2(acc[i][j][0] + bv0, acc[i][j][1] + bv1);
            if (r0 + 8 < M)
                *(float2*)dst1 = make_float2(acc[i][j][2] + bv0, acc[i][j][3] + bv1);
        }
    }
}

// ---------------- int64/int32 edge-index detection --------------------------
__global__ void detect_kernel(const void* ei) {
    const long long* p = (const long long*)ei;
    int ok = 1;
    for (int i = 0; i < 64; i++) {
        long long v = p[i];
        if (v < 0 || v >= NN) { ok = 0; break; }
    }
    g_is64 = ok;
}

// ---------------- init ------------------------------------------------------
__global__ void init_kernel() {
    int i = blockIdx.x * blockDim.x + threadIdx.x;
    if (i < NN * HEADS) { g_m1[i] = 0u; g_s1[i] = 0.f; }
    if (i < NN)         { g_deg[i] = 0; g_m2[i] = 0u; g_s2[i] = 0.f; }
}

// ---------------- layer-1 edge scores (warp per edge) -----------------------
__global__ __launch_bounds__(256) void edge_scores1(const void* ei,
                                                    const float* __restrict__ att)
{
    int gw = (blockIdx.x * blockDim.x + threadIdx.x) >> 5;
    int lane = threadIdx.x & 31;
    if (gw >= ET) return;
    int s = esrc(ei, gw), d = edst(ei, gw);
    const float* xls = g_xl1 + (size_t)s * D1;
    const float* xrd = g_xr1 + (size_t)d * D1;
    #pragma unroll
    for (int h = 0; h < HEADS; h++) {
        int c = h * HID + lane;
        float v0 = lrelu(xls[c] + xrd[c]) * att[c];
        float v1 = lrelu(xls[c + 32] + xrd[c + 32]) * att[c + 32];
        float sum = v0 + v1;
        #pragma unroll
        for (int o = 16; o; o >>= 1) sum += __shfl_xor_sync(0xffffffffu, sum, o);
        if (lane == 0) g_e1[(size_t)gw * HEADS + h] = sum;
    }
}

// ---------------- CSR build -------------------------------------------------
__global__ void deg_kernel(const void* ei) {
    int w = blockIdx.x * blockDim.x + threadIdx.x;
    if (w >= ET) return;
    atomicAdd(&g_deg[edst(ei, w)], 1);
}

__global__ __launch_bounds__(1024) void scan_kernel() {
    __shared__ int sh[1024];
    __shared__ int carry_s;
    int t = threadIdx.x;
    if (t == 0) carry_s = 0;
    __syncthreads();
    for (int base = 0; base < NN; base += 1024) {
        int v = (base + t < NN) ? g_deg[base + t] : 0;
        sh[t] = v;
        __syncthreads();
        for (int o = 1; o < 1024; o <<= 1) {
            int add = (t >= o) ? sh[t - o] : 0;
            __syncthreads();
            sh[t] += add;
            __syncthreads();
        }
        int excl = sh[t] - v + carry_s;
        if (base + t < NN) { g_off[base + t] = excl; g_cur[base + t] = excl; }
        __syncthreads();
        if (t == 0) carry_s += sh[1023];
        __syncthreads();
    }
    if (t == 0) g_off[NN] = carry_s;
}

__global__ void scatter_kernel(const void* ei) {
    int w = blockIdx.x * blockDim.x + threadIdx.x;
    if (w >= ET) return;
    int pos = atomicAdd(&g_cur[edst(ei, w)], 1);
    g_perm[pos] = w;
}

// ---------------- layer-1 softmax stats -------------------------------------
__global__ void max1_kernel(const void* ei) {
    int i = blockIdx.x * blockDim.x + threadIdx.x;
    if (i >= ET * HEADS) return;
    int e = i >> 3, h = i & 7;
    int d = edst(ei, e);
    atomicMax(&g_m1[d * HEADS + h], fenc(g_e1[i]));
}
__global__ void sum1_kernel(const void* ei) {
    int i = blockIdx.x * blockDim.x + threadIdx.x;
    if (i >= ET * HEADS) return;
    int e = i >> 3, h = i & 7;
    int d = edst(ei, e);
    float m = fdec(g_m1[d * HEADS + h]);
    atomicAdd(&g_s1[d * HEADS + h], expf(g_e1[i] - m));
}

// ---------------- layer-1 aggregation (block per dst) -----------------------
__global__ __launch_bounds__(256) void aggregate1(const void* ei,
                                                  const float* __restrict__ bias)
{
    int d = blockIdx.x;
    int beg = g_off[d], end = g_off[d + 1];
    int t = threadIdx.x;
    __shared__ float wsh[32 * 8];
    __shared__ int   ssh[32];
    float mh  = fdec(g_m1[d * HEADS + (t & 7)]);
    float svh = 1.f / (g_s1[d * HEADS + (t & 7)] + 1e-16f);
    float acc0 = 0.f, acc1 = 0.f;
    int h0 = t >> 6, h1 = (t + 256) >> 6;
    for (int ch = beg; ch < end; ch += 32) {
        int nc = min(32, end - ch);
        int i = t >> 3, h = t & 7;
        if (i < nc) {
            int eid = g_perm[ch + i];
            wsh[i * 8 + h] = expf(g_e1[(size_t)eid * HEADS + h] - mh) * svh;
            if (h == 0) ssh[i] = esrc(ei, eid);
        }
        __syncthreads();
        for (int i2 = 0; i2 < nc; i2++) {
            const float* xs = g_xl1 + (size_t)ssh[i2] * D1;
            acc0 += wsh[i2 * 8 + h0] * xs[t];
            acc1 += wsh[i2 * 8 + h1] * xs[t + 256];
        }
        __syncthreads();
    }
    g_h1[(size_t)d * D1 + t]       = fmaxf(acc0 + bias[t], 0.f);
    g_h1[(size_t)d * D1 + t + 256] = fmaxf(acc1 + bias[t + 256], 0.f);
}

// ---------------- layer-2 edge scores (warp per edge, 1 head) ---------------
__global__ __launch_bounds__(256) void edge_scores2(const void* ei,
                                                    const float* __restrict__ att)
{
    int gw = (blockIdx.x * blockDim.x + threadIdx.x) >> 5;
    int lane = threadIdx.x & 31;
    if (gw >= ET) return;
    int s = esrc(ei, gw), d = edst(ei, gw);
    const float* xls = g_xl2 + (size_t)s * D2;
    const float* xrd = g_xr2 + (size_t)d * D2;
    float v0 = lrelu(xls[lane] + xrd[lane]) * att[lane];
    float v1 = lrelu(xls[lane + 32] + xrd[lane + 32]) * att[lane + 32];
    float sum = v0 + v1;
    #pragma unroll
    for (int o = 16; o; o >>= 1) sum += __shfl_xor_sync(0xffffffffu, sum, o);
    if (lane == 0) g_e2[gw] = sum;
}

__global__ void max2_kernel(const void* ei) {
    int w = blockIdx.x * blockDim.x + threadIdx.x;
    if (w >= ET) return;
    atomicMax(&g_m2[edst(ei, w)], fenc(g_e2[w]));
}
__global__ void sum2_kernel(const void* ei) {
    int w = blockIdx.x * blockDim.x + threadIdx.x;
    if (w >= ET) return;
    int d = edst(ei, w);
    atomicAdd(&g_s2[d], expf(g_e2[w] - fdec(g_m2[d])));
}

// ---------------- layer-2 aggregation (block per dst, 64 thr) ---------------
__global__ __launch_bounds__(64) void aggregate2(const void* ei,
                                                 const float* __restrict__ bias)
{
    int d = blockIdx.x;
    int beg = g_off[d], end = g_off[d + 1];
    int t = threadIdx.x;
    __shared__ float wsh[64];
    __shared__ int   ssh[64];
    float mh = fdec(g_m2[d]);
    float sv = 1.f / (g_s2[d] + 1e-16f);
    float acc = 0.f;
    for (int ch = beg; ch < end; ch += 64) {
        int nc = min(64, end - ch);
        if (t < nc) {
            int eid = g_perm[ch + t];
            wsh[t] = expf(g_e2[eid] - mh) * sv;
            ssh[t] = esrc(ei, eid);
        }
        __syncthreads();
        for (int i = 0; i < nc; i++)
            acc += wsh[i] * g_xl2[(size_t)ssh[i] * D2 + t];
        __syncthreads();
    }
    g_h2[(size_t)d * D2 + t] = fmaxf(acc + bias[t], 0.f);
}

// ---------------- launch ----------------------------------------------------
extern "C" void kernel_launch(void* const* d_in, const int* in_sizes, int n_in,
                              void* d_out, int out_size)
{
    const float* x    = (const float*)d_in[0];
    const void*  ei   = d_in[1];
    const float* W1l  = (const float*)d_in[2];
    const float* b1l  = (const float*)d_in[3];
    const float* W1r  = (const float*)d_in[4];
    const float* b1r  = (const float*)d_in[5];
    const float* att1 = (const float*)d_in[6];
    const float* bias1= (const float*)d_in[7];
    const float* W2l  = (const float*)d_in[8];
    const float* b2l  = (const float*)d_in[9];
    const float* W2r  = (const float*)d_in[10];
    const float* b2r  = (const float*)d_in[11];
    const float* att2 = (const float*)d_in[12];
    const float* bias2= (const float*)d_in[13];
    const float* fcw  = (const float*)d_in[14];
    const float* fcb  = (const float*)d_in[15];
    float* out = (float*)d_out;

    void *p_xl1, *p_xr1, *p_h1, *p_xl2, *p_xr2, *p_h2;
    cudaGetSymbolAddress(&p_xl1, g_xl1);
    cudaGetSymbolAddress(&p_xr1, g_xr1);
    cudaGetSymbolAddress(&p_h1,  g_h1);
    cudaGetSymbolAddress(&p_xl2, g_xl2);
    cudaGetSymbolAddress(&p_xr2, g_xr2);
    cudaGetSymbolAddress(&p_h2,  g_h2);

    detect_kernel<<<1, 1>>>(ei);
    init_kernel<<<(NN * HEADS + 255) / 256, 256>>>();

    // layer-1: fused [10000,512] x [1024,512]^T -> xl1 | xr1
    {
        dim3 g(1024 / 128, (NN + 127) / 128);
        tc_gemm<<<g, 256>>>(x, W1l, W1r, b1l, b1r,
                            (float*)p_xl1, (float*)p_xr1, D1, NN, 1024, IND);
    }

    int eb = (ET * 32 + 255) / 256;
    edge_scores1<<<eb, 256>>>(ei, att1);

    deg_kernel<<<(ET + 255) / 256, 256>>>(ei);
    scan_kernel<<<1, 1024>>>();
    scatter_kernel<<<(ET + 255) / 256, 256>>>(ei);

    max1_kernel<<<(ET * HEADS + 255) / 256, 256>>>(ei);
    sum1_kernel<<<(ET * HEADS + 255) / 256, 256>>>(ei);
    aggregate1<<<NN, 256>>>(ei, bias1);

    // layer-2: fused [10000,512] x [128,512]^T -> xl2 | xr2
    {
        dim3 g(1, (NN + 127) / 128);
        tc_gemm<<<g, 256>>>((const float*)p_h1, W2l, W2r, b2l, b2r,
                            (float*)p_xl2, (float*)p_xr2, D2, NN, 128, D1);
    }

    edge_scores2<<<eb, 256>>>(ei, att2);
    max2_kernel<<<(ET + 255) / 256, 256>>>(ei);
    sum2_kernel<<<(ET + 255) / 256, 256>>>(ei);
    aggregate2<<<NN, 64>>>(ei, bias2);

    // FC: [10000,64] x [5000,64]^T -> out
    {
        dim3 g((ODIM + 127) / 128, (NN + 127) / 128);
        tc_gemm<<<g, 256>>>((const float*)p_h2, fcw, fcw, fcb, fcb,
                            out, out, ODIM, NN, ODIM, D2);
    }
}

// round 5
// speedup vs baseline: 2.6577x; 1.1388x over previous
#include <cuda_runtime.h>
#include <cstdint>
#include <math.h>

#define NN    10000
#define IND   512
#define D1    512      // HEADS*HID
#define HEADS 8
#define HID   64
#define D2    64
#define ODIM  5000
#define NE    160000
#define ET    170000   // NE + NN self loops
#define NEG   0.2f

// ---------------- scratch (static device globals; no allocation) ------------
__device__ float    g_xl1[(size_t)NN * D1];
__device__ float    g_xr1[(size_t)NN * D1];
__device__ float    g_h1 [(size_t)NN * D1];
__device__ float    g_xl2[(size_t)NN * D2];
__device__ float    g_xr2[(size_t)NN * D2];
__device__ float    g_h2 [(size_t)NN * D2];
__device__ int      g_deg[NN];
__device__ int      g_off[NN + 1];
__device__ int      g_cur[NN];
__device__ int      g_perm[ET];
__device__ int      g_is64;

// ---------------- helpers ---------------------------------------------------
__device__ __forceinline__ int eidx(const void* ei, int i) {
    return g_is64 ? (int)((const long long*)ei)[i] : ((const int*)ei)[i];
}
__device__ __forceinline__ int esrc(const void* ei, int w) {
    return (w < NE) ? eidx(ei, w) : (w - NE);
}
__device__ __forceinline__ int edst(const void* ei, int w) {
    return (w < NE) ? eidx(ei, NE + w) : (w - NE);
}
__device__ __forceinline__ float lrelu(float v) { return v > 0.f ? v : NEG * v; }
__device__ __forceinline__ uint32_t f2tf32(float f) {
    uint32_t r; asm("cvt.rna.tf32.f32 %0, %1;" : "=r"(r) : "f"(f)); return r;
}

// ---------------- tf32 mma.sync GEMM ----------------------------------------
// C[M,Nc] = A[M,K] @ W[Nc,K]^T + bias ; split into (Wa,ba,Ca | Wb,bb,Cb).
// Tile 128x128, BK=32, 8 warps of 64x32 m16n8k8 tiles. K % 32 == 0.
#define BK 32
#define STR 36

__device__ __forceinline__ void mma16n8k8(float* c, const uint32_t* a, const uint32_t* b) {
    asm volatile("mma.sync.aligned.m16n8k8.row.col.f32.tf32.tf32.f32 "
        "{%0,%1,%2,%3}, {%4,%5,%6,%7}, {%8,%9}, {%0,%1,%2,%3};"
        : "+f"(c[0]), "+f"(c[1]), "+f"(c[2]), "+f"(c[3])
        : "r"(a[0]), "r"(a[1]), "r"(a[2]), "r"(a[3]), "r"(b[0]), "r"(b[1]));
}

__global__ __launch_bounds__(256) void tc_gemm(
    const float* __restrict__ A,
    const float* __restrict__ Wa, const float* __restrict__ Wb,
    const float* __restrict__ ba, const float* __restrict__ bb,
    float* __restrict__ Ca, float* __restrict__ Cb,
    int split, int M, int Nc, int K)
{
    __shared__ uint32_t As[128 * STR];
    __shared__ uint32_t Bs[128 * STR];

    int tid = threadIdx.x, wid = tid >> 5, lane = tid & 31;
    int g = lane >> 2, q = lane & 3;
    int wm = wid >> 2, wn = wid & 3;
    int rowBase = blockIdx.y * 128, colBase = blockIdx.x * 128;

    int srow = tid >> 1;
    int scol = (tid & 1) * 16;
    int garow = rowBase + srow;
    int gbrow = colBase + srow;
    const float* agp = (garow < M) ? A + (size_t)garow * K + scol : nullptr;
    const float* bgp = nullptr;
    if (gbrow < Nc)
        bgp = (gbrow < split) ? Wa + (size_t)gbrow * K + scol
                              : Wb + (size_t)(gbrow - split) * K + scol;

    float acc[4][4][4];
    #pragma unroll
    for (int i = 0; i < 4; i++)
        #pragma unroll
        for (int j = 0; j < 4; j++)
            #pragma unroll
            for (int r = 0; r < 4; r++) acc[i][j][r] = 0.f;

    for (int k0 = 0; k0 < K; k0 += BK) {
        #pragma unroll
        for (int j = 0; j < 4; j++) {
            float4 av = agp ? *(const float4*)(agp + k0 + j * 4)
                            : make_float4(0.f, 0.f, 0.f, 0.f);
            float4 bv = bgp ? *(const float4*)(bgp + k0 + j * 4)
                            : make_float4(0.f, 0.f, 0.f, 0.f);
            uint32_t* ad = &As[srow * STR + scol + j * 4];
            uint32_t* bd = &Bs[srow * STR + scol + j * 4];
            ad[0] = f2tf32(av.x); ad[1] = f2tf32(av.y);
            ad[2] = f2tf32(av.z); ad[3] = f2tf32(av.w);
            bd[0] = f2tf32(bv.x); bd[1] = f2tf32(bv.y);
            bd[2] = f2tf32(bv.z); bd[3] = f2tf32(bv.w);
        }
        __syncthreads();

        #pragma unroll
        for (int kk = 0; kk < BK; kk += 8) {
            uint32_t afr[4][4], bfr[4][2];
            #pragma unroll
            for (int i = 0; i < 4; i++) {
                int r = wm * 64 + i * 16 + g;
                afr[i][0] = As[(r    ) * STR + kk + q    ];
                afr[i][1] = As[(r + 8) * STR + kk + q    ];
                afr[i][2] = As[(r    ) * STR + kk + q + 4];
                afr[i][3] = As[(r + 8) * STR + kk + q + 4];
            }
            #pragma unroll
            for (int j = 0; j < 4; j++) {
                int n = wn * 32 + j * 8 + g;
                bfr[j][0] = Bs[n * STR + kk + q    ];
                bfr[j][1] = Bs[n * STR + kk + q + 4];
            }
            #pragma unroll
            for (int i = 0; i < 4; i++)
                #pragma unroll
                for (int j = 0; j < 4; j++)
                    mma16n8k8(acc[i][j], afr[i], bfr[j]);
        }
        __syncthreads();
    }

    #pragma unroll
    for (int i = 0; i < 4; i++) {
        int r0 = rowBase + wm * 64 + i * 16 + g;
        #pragma unroll
        for (int j = 0; j < 4; j++) {
            int c = colBase + wn * 32 + j * 8 + q * 2;
            if (c >= Nc) continue;
            float bv0, bv1;
            float* dst0; float* dst1;
            if (c < split) {
                bv0 = ba[c]; bv1 = ba[c + 1];
                dst0 = Ca + (size_t)r0 * split + c;
                dst1 = Ca + (size_t)(r0 + 8) * split + c;
            } else {
                int cc = c - split; int w2 = Nc - split;
                bv0 = bb[cc]; bv1 = bb[cc + 1];
                dst0 = Cb + (size_t)r0 * w2 + cc;
                dst1 = Cb + (size_t)(r0 + 8) * w2 + cc;
            }
            if (r0 < M)
                *(float2*)dst0 = make_float2(acc[i][j][0] + bv0, acc[i][j][1] + bv1);
            if (r0 + 8 < M)
                *(float2*)dst1 = make_float2(acc[i][j][2] + bv0, acc[i][j][3] + bv1);
        }
    }
}

// ---------------- int64/int32 edge-index detection --------------------------
__global__ void detect_kernel(const void* ei) {
    const long long* p = (const long long*)ei;
    int ok = 1;
    for (int i = 0; i < 64; i++) {
        long long v = p[i];
        if (v < 0 || v >= NN) { ok = 0; break; }
    }
    g_is64 = ok;
}

__global__ void init_kernel() {
    int i = blockIdx.x * blockDim.x + threadIdx.x;
    if (i < NN) g_deg[i] = 0;
}

// ---------------- CSR build -------------------------------------------------
__global__ void deg_kernel(const void* ei) {
    int w = blockIdx.x * blockDim.x + threadIdx.x;
    if (w >= ET) return;
    atomicAdd(&g_deg[edst(ei, w)], 1);
}

__global__ __launch_bounds__(1024) void scan_kernel() {
    __shared__ int sh[1024];
    __shared__ int carry_s;
    int t = threadIdx.x;
    if (t == 0) carry_s = 0;
    __syncthreads();
    for (int base = 0; base < NN; base += 1024) {
        int v = (base + t < NN) ? g_deg[base + t] : 0;
        sh[t] = v;
        __syncthreads();
        for (int o = 1; o < 1024; o <<= 1) {
            int add = (t >= o) ? sh[t - o] : 0;
            __syncthreads();
            sh[t] += add;
            __syncthreads();
        }
        int excl = sh[t] - v + carry_s;
        if (base + t < NN) { g_off[base + t] = excl; g_cur[base + t] = excl; }
        __syncthreads();
        if (t == 0) carry_s += sh[1023];
        __syncthreads();
    }
    if (t == 0) g_off[NN] = carry_s;
}

__global__ void scatter_kernel(const void* ei) {
    int w = blockIdx.x * blockDim.x + threadIdx.x;
    if (w >= ET) return;
    int pos = atomicAdd(&g_cur[edst(ei, w)], 1);
    g_perm[pos] = w;
}

// ---------------- layer-1 fused score+softmax+aggregate (block per dst) -----
// 8 warps = 8 heads; lane owns channels c0 = wid*64+lane and c1 = c0+32.
// Online softmax over the dst's incoming edges; xl[src] row read exactly once.
__global__ __launch_bounds__(256) void gat1_fused(const void* ei,
                                                  const float* __restrict__ att,
                                                  const float* __restrict__ bias)
{
    int d = blockIdx.x;
    int t = threadIdx.x, wid = t >> 5, lane = t & 31;
    int c0 = wid * 64 + lane, c1 = c0 + 32;

    float xr0 = g_xr1[(size_t)d * D1 + c0];
    float xr1v = g_xr1[(size_t)d * D1 + c1];
    float a0 = att[c0], a1 = att[c1];

    int beg = g_off[d], end = g_off[d + 1];
    float m = -INFINITY, ssum = 0.f, acc0 = 0.f, acc1 = 0.f;

    // prefetch first edge
    int s = esrc(ei, g_perm[beg]);
    float xl0 = g_xl1[(size_t)s * D1 + c0];
    float xl1v = g_xl1[(size_t)s * D1 + c1];

    for (int p = beg; p < end; p++) {
        float cx0 = xl0, cx1 = xl1v;
        if (p + 1 < end) {
            int s2 = esrc(ei, g_perm[p + 1]);
            xl0 = g_xl1[(size_t)s2 * D1 + c0];
            xl1v = g_xl1[(size_t)s2 * D1 + c1];
        }
        float v = lrelu(cx0 + xr0) * a0 + lrelu(cx1 + xr1v) * a1;
        #pragma unroll
        for (int o = 16; o; o >>= 1) v += __shfl_xor_sync(0xffffffffu, v, o);
        float nm = fmaxf(m, v);
        float scale = __expf(m - nm);
        float pw = __expf(v - nm);
        ssum = ssum * scale + pw;
        acc0 = acc0 * scale + pw * cx0;
        acc1 = acc1 * scale + pw * cx1;
        m = nm;
    }
    float inv = 1.f / ssum;
    g_h1[(size_t)d * D1 + c0] = fmaxf(acc0 * inv + bias[c0], 0.f);
    g_h1[(size_t)d * D1 + c1] = fmaxf(acc1 * inv + bias[c1], 0.f);
}

// ---------------- layer-2 fused (warp per dst, 1 head) -----------------------
__global__ __launch_bounds__(256) void gat2_fused(const void* ei,
                                                  const float* __restrict__ att,
                                                  const float* __restrict__ bias)
{
    int d = (blockIdx.x * blockDim.x + threadIdx.x) >> 5;
    if (d >= NN) return;
    int lane = threadIdx.x & 31;
    int c0 = lane, c1 = lane + 32;

    float xr0 = g_xr2[(size_t)d * D2 + c0];
    float xr1v = g_xr2[(size_t)d * D2 + c1];
    float a0 = att[c0], a1 = att[c1];

    int beg = g_off[d], end = g_off[d + 1];
    float m = -INFINITY, ssum = 0.f, acc0 = 0.f, acc1 = 0.f;

    int s = esrc(ei, g_perm[beg]);
    float xl0 = g_xl2[(size_t)s * D2 + c0];
    float xl1v = g_xl2[(size_t)s * D2 + c1];

    for (int p = beg; p < end; p++) {
        float cx0 = xl0, cx1 = xl1v;
        if (p + 1 < end) {
            int s2 = esrc(ei, g_perm[p + 1]);
            xl0 = g_xl2[(size_t)s2 * D2 + c0];
            xl1v = g_xl2[(size_t)s2 * D2 + c1];
        }
        float v = lrelu(cx0 + xr0) * a0 + lrelu(cx1 + xr1v) * a1;
        #pragma unroll
        for (int o = 16; o; o >>= 1) v += __shfl_xor_sync(0xffffffffu, v, o);
        float nm = fmaxf(m, v);
        float scale = __expf(m - nm);
        float pw = __expf(v - nm);
        ssum = ssum * scale + pw;
        acc0 = acc0 * scale + pw * cx0;
        acc1 = acc1 * scale + pw * cx1;
        m = nm;
    }
    float inv = 1.f / ssum;
    g_h2[(size_t)d * D2 + c0] = fmaxf(acc0 * inv + bias[c0], 0.f);
    g_h2[(size_t)d * D2 + c1] = fmaxf(acc1 * inv + bias[c1], 0.f);
}

// ---------------- launch ----------------------------------------------------
extern "C" void kernel_launch(void* const* d_in, const int* in_sizes, int n_in,
                              void* d_out, int out_size)
{
    const float* x    = (const float*)d_in[0];
    const void*  ei   = d_in[1];
    const float* W1l  = (const float*)d_in[2];
    const float* b1l  = (const float*)d_in[3];
    const float* W1r  = (const float*)d_in[4];
    const float* b1r  = (const float*)d_in[5];
    const float* att1 = (const float*)d_in[6];
    const float* bias1= (const float*)d_in[7];
    const float* W2l  = (const float*)d_in[8];
    const float* b2l  = (const float*)d_in[9];
    const float* W2r  = (const float*)d_in[10];
    const float* b2r  = (const float*)d_in[11];
    const float* att2 = (const float*)d_in[12];
    const float* bias2= (const float*)d_in[13];
    const float* fcw  = (const float*)d_in[14];
    const float* fcb  = (const float*)d_in[15];
    float* out = (float*)d_out;

    void *p_xl1, *p_xr1, *p_h1, *p_xl2, *p_xr2, *p_h2;
    cudaGetSymbolAddress(&p_xl1, g_xl1);
    cudaGetSymbolAddress(&p_xr1, g_xr1);
    cudaGetSymbolAddress(&p_h1,  g_h1);
    cudaGetSymbolAddress(&p_xl2, g_xl2);
    cudaGetSymbolAddress(&p_xr2, g_xr2);
    cudaGetSymbolAddress(&p_h2,  g_h2);

    detect_kernel<<<1, 1>>>(ei);
    init_kernel<<<(NN + 255) / 256, 256>>>();

    // CSR build (independent of GEMM)
    deg_kernel<<<(ET + 255) / 256, 256>>>(ei);
    scan_kernel<<<1, 1024>>>();
    scatter_kernel<<<(ET + 255) / 256, 256>>>(ei);

    // layer-1 transform: fused [10000,512] x [1024,512]^T -> xl1 | xr1
    {
        dim3 g(1024 / 128, (NN + 127) / 128);
        tc_gemm<<<g, 256>>>(x, W1l, W1r, b1l, b1r,
                            (float*)p_xl1, (float*)p_xr1, D1, NN, 1024, IND);
    }

    gat1_fused<<<NN, 256>>>(ei, att1, bias1);

    // layer-2 transform: fused [10000,512] x [128,512]^T -> xl2 | xr2
    {
        dim3 g(1, (NN + 127) / 128);
        tc_gemm<<<g, 256>>>((const float*)p_h1, W2l, W2r, b2l, b2r,
                            (float*)p_xl2, (float*)p_xr2, D2, NN, 128, D1);
    }

    gat2_fused<<<(NN * 32 + 255) / 256, 256>>>(ei, att2, bias2);

    // FC: [10000,64] x [5000,64]^T -> out
    {
        dim3 g((ODIM + 127) / 128, (NN + 127) / 128);
        tc_gemm<<<g, 256>>>((const float*)p_h2, fcw, fcw, fcb, fcb,
                            out, out, ODIM, NN, ODIM, D2);
    }
}